// round 2
// baseline (speedup 1.0000x reference)
#include <cuda_runtime.h>
#include <cstdint>

#define NB 64
#define NC 512
#define NHW 768
#define NT 32
#define NPROTO 4000
#define NCLASS 4001

typedef unsigned long long ull;

// ---------------- scratch (device globals; no allocs allowed) ----------------
__device__ float g_C[NT * NB * NC];     // einsum output, time-major [t][b][c]
__device__ float g_G[NB * 3072];        // per-step gate pre-activations: [b][gi(1536) | gh(1536)]
__device__ float g_h[NB * NC];          // GRU hidden state
__device__ ull   g_amax[NB];            // packed (score, inv index) argmax accumulator

// ---------------- helpers ----------------
__device__ __forceinline__ ull ffma2(ull a, ull b, ull c) {
    ull d;
    asm("fma.rn.f32x2 %0, %1, %2, %3;" : "=l"(d) : "l"(a), "l"(b), "l"(c));
    return d;
}
__device__ __forceinline__ float fin(ull v) {
    float2 f = *(float2*)&v;
    return f.x + f.y;
}
// order-preserving float->uint packing, ties prefer lower index (argmax-first semantics)
__device__ __forceinline__ ull packkey(float s, int j) {
    unsigned u = __float_as_uint(s);
    u = (u & 0x80000000u) ? ~u : (u | 0x80000000u);
    return ((ull)u << 32) | (ull)(0xFFFFFFFFu - (unsigned)j);
}

// ---------------- init ----------------
__global__ void k_init() {
    int gid = blockIdx.x * 256 + threadIdx.x;
    if (gid < NB * NC) g_h[gid] = 0.f;
    if (gid < NB) g_amax[gid] = (ull)(0xFFFFFFFFu - (unsigned)(NPROTO + 1)); // sentinel: idx=4001 -> STA
}

// ---------------- einsum: C[t,b,c] = sum_hw feature[b,c,hw] * A[b,t,hw] ----------------
// grid (8 c-tiles, 64 b), 256 threads; tile 32t x 64c, K=768 in 64-chunks, f32x2 inner.
__global__ __launch_bounds__(256) void k_einsum(const float* __restrict__ feat,
                                                const float* __restrict__ A) {
    __shared__ __align__(16) float As[32][66];
    __shared__ __align__(16) float Fs[64][66];
    int b = blockIdx.y, c0 = blockIdx.x * 64, tid = threadIdx.x;
    int ci = tid & 15, ti = tid >> 4;
    int c4 = ci * 4, t2 = ti * 2;
    ull acc[2][4] = {};
    const float* Ab = A + (size_t)b * NT * NHW;
    const float* Fb = feat + (size_t)b * NC * NHW + (size_t)c0 * NHW;
    for (int kc = 0; kc < 12; ++kc) {
        int kb = kc * 64;
#pragma unroll
        for (int i = 0; i < 8; ++i) {
            int idx = tid + i * 256; int r = idx >> 6, cl = idx & 63;
            As[r][cl] = Ab[r * NHW + kb + cl];
        }
#pragma unroll
        for (int i = 0; i < 16; ++i) {
            int idx = tid + i * 256; int r = idx >> 6, cl = idx & 63;
            Fs[r][cl] = Fb[r * NHW + kb + cl];
        }
        __syncthreads();
#pragma unroll 8
        for (int k2 = 0; k2 < 32; ++k2) {
            ull a0 = *(const ull*)&As[t2][2 * k2];
            ull a1 = *(const ull*)&As[t2 + 1][2 * k2];
#pragma unroll
            for (int j = 0; j < 4; ++j) {
                ull fv = *(const ull*)&Fs[c4 + j][2 * k2];
                acc[0][j] = ffma2(a0, fv, acc[0][j]);
                acc[1][j] = ffma2(a1, fv, acc[1][j]);
            }
        }
        __syncthreads();
    }
#pragma unroll
    for (int i = 0; i < 2; ++i) {
        float4 o;
        o.x = fin(acc[i][0]); o.y = fin(acc[i][1]); o.z = fin(acc[i][2]); o.w = fin(acc[i][3]);
        *(float4*)&g_C[(t2 + i) * NB * NC + b * NC + c0 + c4] = o;
    }
}

// ---------------- gates GEMM: gi = [C_t|prev] @ Wih^T, gh = h @ Whh^T ----------------
// grid 144: blocks 0..95 region A (gi, j-tile 16, K=1024), 96..143 region B (gh, j-tile 32, K=512).
// prev is gathered on the fly from chemb via the packed argmax of the previous step.
__global__ __launch_bounds__(256) void k_gates(const float* __restrict__ Wih,
                                               const float* __restrict__ Whh,
                                               const float* __restrict__ semb,
                                               const float* __restrict__ unkv,
                                               const float* __restrict__ sta, int t) {
    __shared__ __align__(16) float Xs[64][66];
    __shared__ __align__(16) float Ws[32][66];
    __shared__ const float* prevp[64];
    int tid = threadIdx.x, bid = blockIdx.x;
    if (tid < 64) {
        unsigned idx = 0xFFFFFFFFu - (unsigned)(g_amax[tid] & 0xFFFFFFFFull);
        prevp[tid] = (idx < NPROTO) ? (semb + (size_t)idx * NC)
                                    : ((idx == NPROTO) ? unkv : sta);
    }
    __syncthreads();
    const float* Ct = g_C + (size_t)t * NB * NC;

    if (bid < 96) {                       // --- region A: gi rows ---
        int j0 = bid * 16;
        int bi = tid & 31, ji = tid >> 5;
        int b2 = bi * 2, j2 = ji * 2;
        ull a00 = 0, a01 = 0, a10 = 0, a11 = 0;
        for (int kc = 0; kc < 16; ++kc) {
            int kb = kc * 64;
#pragma unroll
            for (int i = 0; i < 16; ++i) {
                int idx = tid + i * 256; int r = idx >> 6, cl = idx & 63;
                int k = kb + cl;
                Xs[r][cl] = (k < 512) ? Ct[r * NC + k] : prevp[r][k - 512];
            }
#pragma unroll
            for (int i = 0; i < 4; ++i) {
                int idx = tid + i * 256; int r = idx >> 6, cl = idx & 63;
                Ws[r][cl] = Wih[(size_t)(j0 + r) * 1024 + kb + cl];
            }
            __syncthreads();
#pragma unroll 8
            for (int k2 = 0; k2 < 32; ++k2) {
                ull w0 = *(const ull*)&Ws[j2][2 * k2];
                ull w1 = *(const ull*)&Ws[j2 + 1][2 * k2];
                ull x0 = *(const ull*)&Xs[b2][2 * k2];
                ull x1 = *(const ull*)&Xs[b2 + 1][2 * k2];
                a00 = ffma2(x0, w0, a00); a01 = ffma2(x0, w1, a01);
                a10 = ffma2(x1, w0, a10); a11 = ffma2(x1, w1, a11);
            }
            __syncthreads();
        }
        *(float2*)&g_G[b2 * 3072 + j0 + j2] = make_float2(fin(a00), fin(a01));
        *(float2*)&g_G[(b2 + 1) * 3072 + j0 + j2] = make_float2(fin(a10), fin(a11));
    } else {                              // --- region B: gh rows ---
        int j0 = (bid - 96) * 32;
        int bi = tid & 31, jq = tid >> 5;
        int b2 = bi * 2, j4 = jq * 4;
        ull acc[2][4] = {};
        for (int kc = 0; kc < 8; ++kc) {
            int kb = kc * 64;
#pragma unroll
            for (int i = 0; i < 16; ++i) {
                int idx = tid + i * 256; int r = idx >> 6, cl = idx & 63;
                Xs[r][cl] = g_h[r * NC + kb + cl];
            }
#pragma unroll
            for (int i = 0; i < 8; ++i) {
                int idx = tid + i * 256; int r = idx >> 6, cl = idx & 63;
                Ws[r][cl] = Whh[(size_t)(j0 + r) * NC + kb + cl];
            }
            __syncthreads();
#pragma unroll 8
            for (int k2 = 0; k2 < 32; ++k2) {
                ull x0 = *(const ull*)&Xs[b2][2 * k2];
                ull x1 = *(const ull*)&Xs[b2 + 1][2 * k2];
#pragma unroll
                for (int j = 0; j < 4; ++j) {
                    ull wv = *(const ull*)&Ws[j4 + j][2 * k2];
                    acc[0][j] = ffma2(x0, wv, acc[0][j]);
                    acc[1][j] = ffma2(x1, wv, acc[1][j]);
                }
            }
            __syncthreads();
        }
#pragma unroll
        for (int i = 0; i < 2; ++i) {
            float4 o;
            o.x = fin(acc[i][0]); o.y = fin(acc[i][1]); o.z = fin(acc[i][2]); o.w = fin(acc[i][3]);
            *(float4*)&g_G[(b2 + i) * 3072 + 1536 + j0 + j4] = o;
        }
    }
}

// ---------------- GRU pointwise (fp64 transcendentals: fast-math-proof) ----------------
__global__ void k_pointwise(const float* __restrict__ bih, const float* __restrict__ bhh) {
    int gid = blockIdx.x * 256 + threadIdx.x;   // 0..32767
    int b = gid >> 9, c = gid & 511;
    const float* Gb = g_G + b * 3072;
    float ir = Gb[c]        + bih[c];
    float iz = Gb[512 + c]  + bih[512 + c];
    float inn = Gb[1024 + c] + bih[1024 + c];
    float hr = Gb[1536 + c] + bhh[c];
    float hz = Gb[2048 + c] + bhh[512 + c];
    float hn = Gb[2560 + c] + bhh[1024 + c];
    double r = 1.0 / (1.0 + exp(-(double)(ir + hr)));
    double z = 1.0 / (1.0 + exp(-(double)(iz + hz)));
    double n = tanh((double)inn + r * (double)hn);
    float hold = g_h[gid];
    g_h[gid] = (float)((1.0 - z) * n + z * (double)hold);
    if (gid < NB) g_amax[gid] = 0ull;   // reset for this step's raw/argmax
}

// ---------------- raw GEMM + tens output + argmax ----------------
// grid 125 (j-tiles of 32 over 4000 protos); block 0 also handles the UNK column.
__global__ __launch_bounds__(256) void k_raw(const float* __restrict__ protos,
                                             const float* __restrict__ alphap,
                                             const float* __restrict__ biasp,
                                             const float* __restrict__ unkscrp,
                                             float* __restrict__ out, int t) {
    __shared__ __align__(16) float Hs[64][66];
    __shared__ __align__(16) float Ps[32][66];
    int tid = threadIdx.x;
    int j0 = blockIdx.x * 32;
    int ji = tid & 15, bi = tid >> 4;
    int j2 = ji * 2, b4 = bi * 4;
    ull acc[4][2] = {};
    for (int kc = 0; kc < 8; ++kc) {
        int kb = kc * 64;
#pragma unroll
        for (int i = 0; i < 16; ++i) {
            int idx = tid + i * 256; int r = idx >> 6, cl = idx & 63;
            Hs[r][cl] = g_h[r * NC + kb + cl];
        }
#pragma unroll
        for (int i = 0; i < 8; ++i) {
            int idx = tid + i * 256; int r = idx >> 6, cl = idx & 63;
            Ps[r][cl] = protos[(size_t)(j0 + r) * NC + kb + cl];
        }
        __syncthreads();
#pragma unroll 8
        for (int k2 = 0; k2 < 32; ++k2) {
            ull p0 = *(const ull*)&Ps[j2][2 * k2];
            ull p1 = *(const ull*)&Ps[j2 + 1][2 * k2];
#pragma unroll
            for (int i = 0; i < 4; ++i) {
                ull hv = *(const ull*)&Hs[b4 + i][2 * k2];
                acc[i][0] = ffma2(hv, p0, acc[i][0]);
                acc[i][1] = ffma2(hv, p1, acc[i][1]);
            }
        }
        __syncthreads();
    }
    float alpha = *alphap, bias = *biasp;
    ull best[4];
#pragma unroll
    for (int i = 0; i < 4; ++i) {
        int b = b4 + i;
        float s0 = fin(acc[i][0]) * alpha + bias;
        float s1 = fin(acc[i][1]) * alpha + bias;
        float* orow = out + (size_t)(b * NT + t) * NCLASS + j0;
        orow[j2] = s0;
        orow[j2 + 1] = s1;
        ull k0 = packkey(s0, j0 + j2), k1 = packkey(s1, j0 + j2 + 1);
        best[i] = (k0 > k1) ? k0 : k1;
    }
#pragma unroll
    for (int off = 8; off >= 1; off >>= 1) {
#pragma unroll
        for (int i = 0; i < 4; ++i) {
            ull o = __shfl_xor_sync(0xFFFFFFFFu, best[i], off);
            if (o > best[i]) best[i] = o;
        }
    }
    if (ji == 0) {
#pragma unroll
        for (int i = 0; i < 4; ++i) atomicMax(&g_amax[b4 + i], best[i]);
    }
    if (blockIdx.x == 0 && tid < NB) {
        float us = *unkscrp;
        out[(size_t)(tid * NT + t) * NCLASS + NPROTO] = us;
        atomicMax(&g_amax[tid], packkey(us, NPROTO));
    }
}

// ---------------- launch ----------------
extern "C" void kernel_launch(void* const* d_in, const int* in_sizes, int n_in,
                              void* d_out, int out_size) {
    const float* feature = (const float*)d_in[0];
    const float* A       = (const float*)d_in[1];
    const float* protos  = (const float*)d_in[2];
    const float* semb    = (const float*)d_in[3];
    const float* sta     = (const float*)d_in[4];
    const float* unkv    = (const float*)d_in[5];
    const float* Wih     = (const float*)d_in[6];
    const float* Whh     = (const float*)d_in[7];
    const float* bih     = (const float*)d_in[8];
    const float* bhh     = (const float*)d_in[9];
    const float* alphap  = (const float*)d_in[10];
    const float* biasp   = (const float*)d_in[11];
    const float* unkscrp = (const float*)d_in[12];
    float* out = (float*)d_out;

    // out_attns = A reshaped: plain copy into the second output region
    size_t offA = (size_t)NB * NT * NCLASS;
    cudaMemcpyAsync(out + offA, A, sizeof(float) * (size_t)NB * NT * NHW,
                    cudaMemcpyDeviceToDevice);

    k_init<<<128, 256>>>();
    k_einsum<<<dim3(8, 64), 256>>>(feature, A);
    for (int t = 0; t < NT; ++t) {
        k_gates<<<144, 256>>>(Wih, Whh, semb, unkv, sta, t);
        k_pointwise<<<128, 256>>>(bih, bhh);
        k_raw<<<125, 256>>>(protos, alphap, biasp, unkscrp, out, t);
    }
}

// round 5
// speedup vs baseline: 1.0549x; 1.0549x over previous
#include <cuda_runtime.h>
#include <cstdint>

#define NB 64
#define NC 512
#define NHW 768
#define NT 32
#define NPROTO 4000
#define NCLASS 4001
#define GRID 128
#define TPB 256
#define BUFF 7392              // 112 rows * 66 floats per double-buffer half
#define SMEM_BYTES (2*BUFF*4)  // 59136 B

typedef unsigned long long ull;

// ---------------- scratch (device globals; no allocs allowed) ----------------
__device__ float g_C[NT * NB * NC];
__device__ float g_G[NB * 3072];
__device__ float g_h[NB * NC];
__device__ ull   g_amax[NB];
__device__ unsigned g_barcnt;    // returns to 0 after every completed barrier
__device__ unsigned g_barsense;  // monotonically increasing across launches

// ---------------- helpers ----------------
static __device__ __forceinline__ ull ffma2(ull a, ull b, ull c) {
    ull d;
    asm("fma.rn.f32x2 %0, %1, %2, %3;" : "=l"(d) : "l"(a), "l"(b), "l"(c));
    return d;
}
static __device__ __forceinline__ float fin(ull v) {
    float2 f = *(float2*)&v;
    return f.x + f.y;
}
// order-preserving float->uint packing; ties prefer lower index (argmax-first)
static __device__ __forceinline__ ull packkey(float s, int j) {
    unsigned u = __float_as_uint(s);
    u = (u & 0x80000000u) ? ~u : (u | 0x80000000u);
    return ((ull)u << 32) | (ull)(0xFFFFFFFFu - (unsigned)j);
}

// software grid barrier: release-arrive / acquire-spin, monotonic sense
static __device__ __forceinline__ void gridbar(unsigned& phase) {
    __syncthreads();
    if (threadIdx.x == 0) {
        phase += 1;
        unsigned old;
        asm volatile("atom.release.gpu.global.add.u32 %0,[%1],%2;"
                     : "=r"(old) : "l"(&g_barcnt), "r"(1u) : "memory");
        if (old == GRID - 1u) {
            g_barcnt = 0u;
            asm volatile("st.release.gpu.global.u32 [%0],%1;"
                         :: "l"(&g_barsense), "r"(phase) : "memory");
        } else {
            unsigned v;
            for (;;) {
                asm volatile("ld.acquire.gpu.global.u32 %0,[%1];"
                             : "=r"(v) : "l"(&g_barsense) : "memory");
                if (v == phase) break;
                __nanosleep(32);
            }
        }
    }
    __syncthreads();
}

extern __shared__ float S[];
#define XSM(bf,r,c) S[(bf)*BUFF + (r)*66 + (c)]           // 64-row region
#define WSM(bf,r,c) S[(bf)*BUFF + 4224 + (r)*66 + (c)]    // up-to-48-row region

// tile loaders -----------------------------------------------------------
#define ES_LOAD(bf, kc_) do { int kb = (kc_)*64;                                        \
    _Pragma("unroll") for (int i_ = 0; i_ < 8; ++i_) {                                  \
        int idx = tid + i_*256; int r = idx >> 6, cl = idx & 63;                        \
        WSM(bf, r, cl) = Ab[r * NHW + kb + cl]; }                                       \
    _Pragma("unroll") for (int i_ = 0; i_ < 16; ++i_) {                                 \
        int idx = tid + i_*256; int r = idx >> 6, cl = idx & 63;                        \
        XSM(bf, r, cl) = Fb[(size_t)r * NHW + kb + cl]; } } while (0)

#define GA_LOAD(bf, kc_) do { int kb = (kc_)*64;                                        \
    _Pragma("unroll") for (int i_ = 0; i_ < 16; ++i_) {                                 \
        int idx = tid + i_*256; int r = idx >> 6, cl = idx & 63; int k = kb + cl;       \
        XSM(bf, r, cl) = (k < 512) ? Ct[r * 512 + k] : prevp[r][k - 512]; }             \
    _Pragma("unroll") for (int i_ = 0; i_ < 4; ++i_) {                                  \
        int idx = tid + i_*256; int r = idx >> 6, cl = idx & 63;                        \
        WSM(bf, r, cl) = Wih[(size_t)(j0 + r) * 1024 + kb + cl]; } } while (0)

#define GB_LOAD(bf, kc_) do { int kb = (kc_)*64;                                        \
    _Pragma("unroll") for (int i_ = 0; i_ < 16; ++i_) {                                 \
        int idx = tid + i_*256; int r = idx >> 6, cl = idx & 63;                        \
        XSM(bf, r, cl) = g_h[r * 512 + kb + cl]; }                                      \
    _Pragma("unroll") for (int i_ = 0; i_ < 12; ++i_) {                                 \
        int idx = tid + i_*256; int r = idx >> 6, cl = idx & 63;                        \
        WSM(bf, r, cl) = Whh[(size_t)(j0 + r) * 512 + kb + cl]; } } while (0)

#define RW_LOAD(bf, kc_) do { int kb = (kc_)*64;                                        \
    _Pragma("unroll") for (int i_ = 0; i_ < 16; ++i_) {                                 \
        int idx = tid + i_*256; int r = idx >> 6, cl = idx & 63;                        \
        XSM(bf, r, cl) = g_h[r * 512 + kb + cl]; }                                      \
    _Pragma("unroll") for (int i_ = 0; i_ < 8; ++i_) {                                  \
        int idx = tid + i_*256; int r = idx >> 6, cl = idx & 63;                        \
        WSM(bf, r, cl) = protos[(size_t)(j0 + r) * 512 + kb + cl]; } } while (0)

__global__ __launch_bounds__(TPB)
void mega(const float* __restrict__ feat, const float* __restrict__ A,
          const float* __restrict__ protos, const float* __restrict__ semb,
          const float* __restrict__ sta, const float* __restrict__ unkv,
          const float* __restrict__ Wih, const float* __restrict__ Whh,
          const float* __restrict__ bih, const float* __restrict__ bhh,
          const float* __restrict__ alphap, const float* __restrict__ biasp,
          const float* __restrict__ unkscrp, float* __restrict__ out) {
    __shared__ const float* prevp[64];
    const int tid = threadIdx.x, bid = blockIdx.x;
    const int gid = bid * TPB + tid;               // 0..32767, exactly NB*NC
    unsigned phase = *(volatile unsigned*)&g_barsense;  // stable before 1st barrier

    const float alpha = *alphap, bias = *biasp, unkscr = *unkscrp;

    // ---------------- phase 0: init + out_attns copy + einsum ----------------
    g_h[gid] = 0.f;
    if (gid < NB) g_amax[gid] = (ull)(0xFFFFFFFFu - (unsigned)(NPROTO + 1)); // -> STA

    {   // copy A -> out_attns region
        const float4* A4 = (const float4*)A;
        float4* O4 = (float4*)(out + (size_t)NB * NT * NCLASS);
        for (int i = gid; i < NB * NT * NHW / 4; i += GRID * TPB) O4[i] = A4[i];
    }

    {   // einsum: 512 units of (32t x 64c), 4 per block
        const int ci = tid & 15, ti = tid >> 4;    // ci: c-group, ti: t-pair
        const int t2 = ti * 2;
        for (int u = bid; u < 512; u += GRID) {
            const int b = u & 63, c0 = (u >> 6) << 6;
            const float* Ab = A + (size_t)b * NT * NHW;
            const float* Fb = feat + (size_t)b * NC * NHW + (size_t)c0 * NHW;
            ull acc[2][4] = {};
            ES_LOAD(0, 0);
            __syncthreads();
#pragma unroll 2
            for (int kc = 0; kc < 12; ++kc) {
                int cur = kc & 1;
                if (kc < 11) ES_LOAD(cur ^ 1, kc + 1);
#pragma unroll 8
                for (int k2 = 0; k2 < 32; ++k2) {
                    ull a0 = *(const ull*)&WSM(cur, t2, 2 * k2);
                    ull a1 = *(const ull*)&WSM(cur, t2 + 1, 2 * k2);
#pragma unroll
                    for (int j = 0; j < 4; ++j) {
                        ull fv = *(const ull*)&XSM(cur, ci + 16 * j, 2 * k2);
                        acc[0][j] = ffma2(a0, fv, acc[0][j]);
                        acc[1][j] = ffma2(a1, fv, acc[1][j]);
                    }
                }
                __syncthreads();
            }
#pragma unroll
            for (int i = 0; i < 2; ++i)
#pragma unroll
                for (int j = 0; j < 4; ++j)
                    g_C[(t2 + i) * NB * NC + b * NC + c0 + ci + 16 * j] = fin(acc[i][j]);
            __syncthreads();
        }
    }
    gridbar(phase);

    // ---------------- time loop ----------------
    for (int t = 0; t < NT; ++t) {
        // ---- gates: 128 units (96 gi j-16 K1024 | 32 gh j-48 K512) ----
        if (tid < 64) {
            unsigned idx = 0xFFFFFFFFu - (unsigned)(g_amax[tid] & 0xFFFFFFFFull);
            prevp[tid] = (idx < NPROTO) ? (semb + (size_t)idx * NC)
                                        : ((idx == NPROTO) ? unkv : sta);
        }
        __syncthreads();
        const float* Ct = g_C + (size_t)t * NB * NC;

        if (bid < 96) {                       // gi: j0..j0+15, K=1024
            const int j0 = bid << 4;
            const int bi = tid & 31, ji = tid >> 5;   // ji uniform per warp -> bcast
            ull a00 = 0, a01 = 0, a10 = 0, a11 = 0;
            GA_LOAD(0, 0);
            __syncthreads();
#pragma unroll 2
            for (int kc = 0; kc < 16; ++kc) {
                int cur = kc & 1;
                if (kc < 15) GA_LOAD(cur ^ 1, kc + 1);
#pragma unroll 8
                for (int k2 = 0; k2 < 32; ++k2) {
                    ull w0 = *(const ull*)&WSM(cur, ji, 2 * k2);
                    ull w1 = *(const ull*)&WSM(cur, ji + 8, 2 * k2);
                    ull x0 = *(const ull*)&XSM(cur, bi, 2 * k2);
                    ull x1 = *(const ull*)&XSM(cur, bi + 32, 2 * k2);
                    a00 = ffma2(x0, w0, a00); a01 = ffma2(x0, w1, a01);
                    a10 = ffma2(x1, w0, a10); a11 = ffma2(x1, w1, a11);
                }
                __syncthreads();
            }
            g_G[bi * 3072 + j0 + ji]            = fin(a00);
            g_G[bi * 3072 + j0 + ji + 8]        = fin(a01);
            g_G[(bi + 32) * 3072 + j0 + ji]     = fin(a10);
            g_G[(bi + 32) * 3072 + j0 + ji + 8] = fin(a11);
        } else {                              // gh: j0..j0+47, K=512
            const int j0 = (bid - 96) * 48;
            const int bi = tid & 15, jq = tid >> 4;
            ull acc[4][3] = {};
            GB_LOAD(0, 0);
            __syncthreads();
#pragma unroll 2
            for (int kc = 0; kc < 8; ++kc) {
                int cur = kc & 1;
                if (kc < 7) GB_LOAD(cur ^ 1, kc + 1);
#pragma unroll 8
                for (int k2 = 0; k2 < 32; ++k2) {
                    ull wv0 = *(const ull*)&WSM(cur, jq, 2 * k2);
                    ull wv1 = *(const ull*)&WSM(cur, jq + 16, 2 * k2);
                    ull wv2 = *(const ull*)&WSM(cur, jq + 32, 2 * k2);
#pragma unroll
                    for (int i = 0; i < 4; ++i) {
                        ull hv = *(const ull*)&XSM(cur, bi + 16 * i, 2 * k2);
                        acc[i][0] = ffma2(hv, wv0, acc[i][0]);
                        acc[i][1] = ffma2(hv, wv1, acc[i][1]);
                        acc[i][2] = ffma2(hv, wv2, acc[i][2]);
                    }
                }
                __syncthreads();
            }
#pragma unroll
            for (int i = 0; i < 4; ++i)
#pragma unroll
                for (int j = 0; j < 3; ++j)
                    g_G[(bi + 16 * i) * 3072 + 1536 + j0 + jq + 16 * j] = fin(acc[i][j]);
        }
        gridbar(phase);

        // ---- GRU pointwise (fp64 transcendentals: fast-math-proof) ----
        {
            const int b = gid >> 9, c = gid & 511;
            const float* Gb = g_G + b * 3072;
            float ir = Gb[c]        + bih[c];
            float iz = Gb[512 + c]  + bih[512 + c];
            float inn = Gb[1024 + c] + bih[1024 + c];
            float hr = Gb[1536 + c] + bhh[c];
            float hz = Gb[2048 + c] + bhh[512 + c];
            float hn = Gb[2560 + c] + bhh[1024 + c];
            double r = 1.0 / (1.0 + exp(-(double)(ir + hr)));
            double z = 1.0 / (1.0 + exp(-(double)(iz + hz)));
            double n = tanh((double)inn + r * (double)hn);
            float hold = g_h[gid];
            g_h[gid] = (float)((1.0 - z) * n + z * (double)hold);
            if (gid < NB) g_amax[gid] = 0ull;          // reset for this step's argmax
        }
        gridbar(phase);

        // ---- raw scores + tens output + argmax: 125 units (j-tile 32, K=512) ----
        if (bid < 125) {
            const int j0 = bid * 32;
            const int ji = tid & 15, bi = tid >> 4;
            ull acc[4][2] = {};
            RW_LOAD(0, 0);
            __syncthreads();
#pragma unroll 2
            for (int kc = 0; kc < 8; ++kc) {
                int cur = kc & 1;
                if (kc < 7) RW_LOAD(cur ^ 1, kc + 1);
#pragma unroll 8
                for (int k2 = 0; k2 < 32; ++k2) {
                    ull p0 = *(const ull*)&WSM(cur, ji, 2 * k2);
                    ull p1 = *(const ull*)&WSM(cur, ji + 16, 2 * k2);
#pragma unroll
                    for (int i = 0; i < 4; ++i) {
                        ull hv = *(const ull*)&XSM(cur, bi + 16 * i, 2 * k2);
                        acc[i][0] = ffma2(hv, p0, acc[i][0]);
                        acc[i][1] = ffma2(hv, p1, acc[i][1]);
                    }
                }
                __syncthreads();
            }
            ull best[4];
#pragma unroll
            for (int i = 0; i < 4; ++i) {
                int b = bi + 16 * i;
                float s0 = fin(acc[i][0]) * alpha + bias;
                float s1 = fin(acc[i][1]) * alpha + bias;
                float* orow = out + ((size_t)b * NT + t) * NCLASS + j0;
                orow[ji] = s0;
                orow[ji + 16] = s1;
                ull k0 = packkey(s0, j0 + ji), k1 = packkey(s1, j0 + ji + 16);
                best[i] = (k0 > k1) ? k0 : k1;
            }
#pragma unroll
            for (int off = 8; off >= 1; off >>= 1)
#pragma unroll
                for (int i = 0; i < 4; ++i) {
                    ull o = __shfl_xor_sync(0xFFFFFFFFu, best[i], off);
                    if (o > best[i]) best[i] = o;
                }
            if (ji == 0)
#pragma unroll
                for (int i = 0; i < 4; ++i) atomicMax(&g_amax[bi + 16 * i], best[i]);
            if (bid == 0 && tid < NB) {   // UNK column
                out[((size_t)tid * NT + t) * NCLASS + NPROTO] = unkscr;
                atomicMax(&g_amax[tid], packkey(unkscr, NPROTO));
            }
        }
        gridbar(phase);
    }
}

// ---------------- launch ----------------
extern "C" void kernel_launch(void* const* d_in, const int* in_sizes, int n_in,
                              void* d_out, int out_size) {
    const float* feature = (const float*)d_in[0];
    const float* A       = (const float*)d_in[1];
    const float* protos  = (const float*)d_in[2];
    const float* semb    = (const float*)d_in[3];
    const float* sta     = (const float*)d_in[4];
    const float* unkv    = (const float*)d_in[5];
    const float* Wih     = (const float*)d_in[6];
    const float* Whh     = (const float*)d_in[7];
    const float* bih     = (const float*)d_in[8];
    const float* bhh     = (const float*)d_in[9];
    const float* alphap  = (const float*)d_in[10];
    const float* biasp   = (const float*)d_in[11];
    const float* unkscrp = (const float*)d_in[12];
    float* out = (float*)d_out;

    cudaFuncSetAttribute(mega, cudaFuncAttributeMaxDynamicSharedMemorySize, SMEM_BYTES);
    mega<<<GRID, TPB, SMEM_BYTES>>>(feature, A, protos, semb, sta, unkv,
                                    Wih, Whh, bih, bhh, alphap, biasp, unkscrp, out);
}

// round 6
// speedup vs baseline: 1.0585x; 1.0034x over previous
#include <cuda_runtime.h>
#include <cstdint>

#define NB 64
#define NC 512
#define NHW 768
#define NT 32
#define NPROTO 4000
#define NCLASS 4001
#define GRID 128
#define TPB 256
#define BUFF 7392              // 112 rows * 66 floats per double-buffer half
#define SMEM_BYTES (2*BUFF*4)  // 59136 B

typedef unsigned long long ull;

// ---------------- scratch (device globals; no allocs allowed) ----------------
__device__ float g_C[NT * NB * NC];
__device__ float g_G[NB * 3072];
__device__ float g_h[NB * NC];
__device__ ull   g_amax[NB];
__device__ unsigned g_barcnt;    // returns to 0 after every completed barrier
__device__ unsigned g_barsense;  // monotonically increasing across launches

// ---------------- helpers ----------------
static __device__ __forceinline__ ull ffma2(ull a, ull b, ull c) {
    ull d;
    asm("fma.rn.f32x2 %0, %1, %2, %3;" : "=l"(d) : "l"(a), "l"(b), "l"(c));
    return d;
}
static __device__ __forceinline__ float fin(ull v) {
    float2 f = *(float2*)&v;
    return f.x + f.y;
}
// order-preserving float->uint packing; ties prefer lower index (argmax-first)
static __device__ __forceinline__ ull packkey(float s, int j) {
    unsigned u = __float_as_uint(s);
    u = (u & 0x80000000u) ? ~u : (u | 0x80000000u);
    return ((ull)u << 32) | (ull)(0xFFFFFFFFu - (unsigned)j);
}

// software grid barrier: release-arrive / acquire-spin, monotonic sense
static __device__ __forceinline__ void gridbar(unsigned& phase) {
    __syncthreads();
    if (threadIdx.x == 0) {
        phase += 1;
        unsigned old;
        asm volatile("atom.release.gpu.global.add.u32 %0,[%1],%2;"
                     : "=r"(old) : "l"(&g_barcnt), "r"(1u) : "memory");
        if (old == GRID - 1u) {
            g_barcnt = 0u;
            asm volatile("st.release.gpu.global.u32 [%0],%1;"
                         :: "l"(&g_barsense), "r"(phase) : "memory");
        } else {
            unsigned v;
            for (;;) {
                asm volatile("ld.acquire.gpu.global.u32 %0,[%1];"
                             : "=r"(v) : "l"(&g_barsense) : "memory");
                if (v == phase) break;
                __nanosleep(32);
            }
        }
    }
    __syncthreads();
}

extern __shared__ float S[];
#define XSM(bf,r,c) S[(bf)*BUFF + (r)*66 + (c)]           // 64-row region
#define WSM(bf,r,c) S[(bf)*BUFF + 4224 + (r)*66 + (c)]    // up-to-48-row region

// tile loaders -----------------------------------------------------------
#define ES_LOAD(bf, kc_) do { int kb = (kc_)*64;                                        \
    _Pragma("unroll") for (int i_ = 0; i_ < 8; ++i_) {                                  \
        int idx = tid + i_*256; int r = idx >> 6, cl = idx & 63;                        \
        WSM(bf, r, cl) = Ab[r * NHW + kb + cl]; }                                       \
    _Pragma("unroll") for (int i_ = 0; i_ < 16; ++i_) {                                 \
        int idx = tid + i_*256; int r = idx >> 6, cl = idx & 63;                        \
        XSM(bf, r, cl) = Fb[(size_t)r * NHW + kb + cl]; } } while (0)

#define GA_LOAD(bf, kc_) do { int kb = (kc_)*64;                                        \
    _Pragma("unroll") for (int i_ = 0; i_ < 16; ++i_) {                                 \
        int idx = tid + i_*256; int r = idx >> 6, cl = idx & 63; int k = kb + cl;       \
        XSM(bf, r, cl) = (k < 512) ? Ct[r * 512 + k] : prevp[r][k - 512]; }             \
    _Pragma("unroll") for (int i_ = 0; i_ < 4; ++i_) {                                  \
        int idx = tid + i_*256; int r = idx >> 6, cl = idx & 63;                        \
        WSM(bf, r, cl) = Wih[(size_t)(j0 + r) * 1024 + kb + cl]; } } while (0)

#define GB_LOAD(bf, kc_) do { int kb = (kc_)*64;                                        \
    _Pragma("unroll") for (int i_ = 0; i_ < 16; ++i_) {                                 \
        int idx = tid + i_*256; int r = idx >> 6, cl = idx & 63;                        \
        XSM(bf, r, cl) = g_h[r * 512 + kb + cl]; }                                      \
    _Pragma("unroll") for (int i_ = 0; i_ < 12; ++i_) {                                 \
        int idx = tid + i_*256; int r = idx >> 6, cl = idx & 63;                        \
        WSM(bf, r, cl) = Whh[(size_t)(j0 + r) * 512 + kb + cl]; } } while (0)

#define RW_LOAD(bf, kc_) do { int kb = (kc_)*64;                                        \
    _Pragma("unroll") for (int i_ = 0; i_ < 16; ++i_) {                                 \
        int idx = tid + i_*256; int r = idx >> 6, cl = idx & 63;                        \
        XSM(bf, r, cl) = g_h[r * 512 + kb + cl]; }                                      \
    _Pragma("unroll") for (int i_ = 0; i_ < 8; ++i_) {                                  \
        int idx = tid + i_*256; int r = idx >> 6, cl = idx & 63;                        \
        WSM(bf, r, cl) = protos[(size_t)(j0 + r) * 512 + kb + cl]; } } while (0)

__global__ __launch_bounds__(TPB)
void mega(const float* __restrict__ feat, const float* __restrict__ A,
          const float* __restrict__ protos, const float* __restrict__ semb,
          const float* __restrict__ sta, const float* __restrict__ unkv,
          const float* __restrict__ Wih, const float* __restrict__ Whh,
          const float* __restrict__ bih, const float* __restrict__ bhh,
          const float* __restrict__ alphap, const float* __restrict__ biasp,
          const float* __restrict__ unkscrp, float* __restrict__ out) {
    __shared__ const float* prevp[64];
    const int tid = threadIdx.x, bid = blockIdx.x;
    const int gid = bid * TPB + tid;               // 0..32767, exactly NB*NC
    unsigned phase = *(volatile unsigned*)&g_barsense;  // stable before 1st barrier

    const float alpha = *alphap, bias = *biasp, unkscr = *unkscrp;

    // ---------------- phase 0: init + out_attns copy + einsum ----------------
    g_h[gid] = 0.f;
    if (gid < NB) g_amax[gid] = (ull)(0xFFFFFFFFu - (unsigned)(NPROTO + 1)); // -> STA

    {   // copy A -> out_attns region
        const float4* A4 = (const float4*)A;
        float4* O4 = (float4*)(out + (size_t)NB * NT * NCLASS);
        for (int i = gid; i < NB * NT * NHW / 4; i += GRID * TPB) O4[i] = A4[i];
    }

    {   // einsum: 512 units of (32t x 64c), 4 per block
        const int ci = tid & 15, ti = tid >> 4;    // ci: c-group, ti: t-pair
        const int t2 = ti * 2;
        for (int u = bid; u < 512; u += GRID) {
            const int b = u & 63, c0 = (u >> 6) << 6;
            const float* Ab = A + (size_t)b * NT * NHW;
            const float* Fb = feat + (size_t)b * NC * NHW + (size_t)c0 * NHW;
            ull acc[2][4] = {};
            ES_LOAD(0, 0);
            __syncthreads();
#pragma unroll 2
            for (int kc = 0; kc < 12; ++kc) {
                int cur = kc & 1;
                if (kc < 11) ES_LOAD(cur ^ 1, kc + 1);
#pragma unroll 8
                for (int k2 = 0; k2 < 32; ++k2) {
                    ull a0 = *(const ull*)&WSM(cur, t2, 2 * k2);
                    ull a1 = *(const ull*)&WSM(cur, t2 + 1, 2 * k2);
#pragma unroll
                    for (int j = 0; j < 4; ++j) {
                        ull fv = *(const ull*)&XSM(cur, ci + 16 * j, 2 * k2);
                        acc[0][j] = ffma2(a0, fv, acc[0][j]);
                        acc[1][j] = ffma2(a1, fv, acc[1][j]);
                    }
                }
                __syncthreads();
            }
#pragma unroll
            for (int i = 0; i < 2; ++i)
#pragma unroll
                for (int j = 0; j < 4; ++j)
                    g_C[(t2 + i) * NB * NC + b * NC + c0 + ci + 16 * j] = fin(acc[i][j]);
            __syncthreads();
        }
    }
    gridbar(phase);

    // ---------------- time loop ----------------
    for (int t = 0; t < NT; ++t) {
        // ---- gates: 128 units (96 gi j-16 K1024 | 32 gh j-48 K512) ----
        if (tid < 64) {
            unsigned idx = 0xFFFFFFFFu - (unsigned)(g_amax[tid] & 0xFFFFFFFFull);
            prevp[tid] = (idx < NPROTO) ? (semb + (size_t)idx * NC)
                                        : ((idx == NPROTO) ? unkv : sta);
        }
        __syncthreads();
        const float* Ct = g_C + (size_t)t * NB * NC;

        if (bid < 96) {                       // gi: j0..j0+15, K=1024
            const int j0 = bid << 4;
            const int bi = tid & 31, ji = tid >> 5;   // ji uniform per warp -> bcast
            ull a00 = 0, a01 = 0, a10 = 0, a11 = 0;
            GA_LOAD(0, 0);
            __syncthreads();
#pragma unroll 2
            for (int kc = 0; kc < 16; ++kc) {
                int cur = kc & 1;
                if (kc < 15) GA_LOAD(cur ^ 1, kc + 1);
#pragma unroll 8
                for (int k2 = 0; k2 < 32; ++k2) {
                    ull w0 = *(const ull*)&WSM(cur, ji, 2 * k2);
                    ull w1 = *(const ull*)&WSM(cur, ji + 8, 2 * k2);
                    ull x0 = *(const ull*)&XSM(cur, bi, 2 * k2);
                    ull x1 = *(const ull*)&XSM(cur, bi + 32, 2 * k2);
                    a00 = ffma2(x0, w0, a00); a01 = ffma2(x0, w1, a01);
                    a10 = ffma2(x1, w0, a10); a11 = ffma2(x1, w1, a11);
                }
                __syncthreads();
            }
            g_G[bi * 3072 + j0 + ji]            = fin(a00);
            g_G[bi * 3072 + j0 + ji + 8]        = fin(a01);
            g_G[(bi + 32) * 3072 + j0 + ji]     = fin(a10);
            g_G[(bi + 32) * 3072 + j0 + ji + 8] = fin(a11);
        } else {                              // gh: j0..j0+47, K=512
            const int j0 = (bid - 96) * 48;
            const int bi = tid & 15, jq = tid >> 4;
            ull acc[4][3] = {};
            GB_LOAD(0, 0);
            __syncthreads();
#pragma unroll 2
            for (int kc = 0; kc < 8; ++kc) {
                int cur = kc & 1;
                if (kc < 7) GB_LOAD(cur ^ 1, kc + 1);
#pragma unroll 8
                for (int k2 = 0; k2 < 32; ++k2) {
                    ull wv0 = *(const ull*)&WSM(cur, jq, 2 * k2);
                    ull wv1 = *(const ull*)&WSM(cur, jq + 16, 2 * k2);
                    ull wv2 = *(const ull*)&WSM(cur, jq + 32, 2 * k2);
#pragma unroll
                    for (int i = 0; i < 4; ++i) {
                        ull hv = *(const ull*)&XSM(cur, bi + 16 * i, 2 * k2);
                        acc[i][0] = ffma2(hv, wv0, acc[i][0]);
                        acc[i][1] = ffma2(hv, wv1, acc[i][1]);
                        acc[i][2] = ffma2(hv, wv2, acc[i][2]);
                    }
                }
                __syncthreads();
            }
#pragma unroll
            for (int i = 0; i < 4; ++i)
#pragma unroll
                for (int j = 0; j < 3; ++j)
                    g_G[(bi + 16 * i) * 3072 + 1536 + j0 + jq + 16 * j] = fin(acc[i][j]);
        }
        gridbar(phase);

        // ---- GRU pointwise (fp64 transcendentals: fast-math-proof) ----
        {
            const int b = gid >> 9, c = gid & 511;
            const float* Gb = g_G + b * 3072;
            float ir = Gb[c]        + bih[c];
            float iz = Gb[512 + c]  + bih[512 + c];
            float inn = Gb[1024 + c] + bih[1024 + c];
            float hr = Gb[1536 + c] + bhh[c];
            float hz = Gb[2048 + c] + bhh[512 + c];
            float hn = Gb[2560 + c] + bhh[1024 + c];
            double r = 1.0 / (1.0 + exp(-(double)(ir + hr)));
            double z = 1.0 / (1.0 + exp(-(double)(iz + hz)));
            double n = tanh((double)inn + r * (double)hn);
            float hold = g_h[gid];
            g_h[gid] = (float)((1.0 - z) * n + z * (double)hold);
            if (gid < NB) g_amax[gid] = 0ull;          // reset for this step's argmax
        }
        gridbar(phase);

        // ---- raw scores + tens output + argmax: 125 units (j-tile 32, K=512) ----
        if (bid < 125) {
            const int j0 = bid * 32;
            const int ji = tid & 15, bi = tid >> 4;
            ull acc[4][2] = {};
            RW_LOAD(0, 0);
            __syncthreads();
#pragma unroll 2
            for (int kc = 0; kc < 8; ++kc) {
                int cur = kc & 1;
                if (kc < 7) RW_LOAD(cur ^ 1, kc + 1);
#pragma unroll 8
                for (int k2 = 0; k2 < 32; ++k2) {
                    ull p0 = *(const ull*)&WSM(cur, ji, 2 * k2);
                    ull p1 = *(const ull*)&WSM(cur, ji + 16, 2 * k2);
#pragma unroll
                    for (int i = 0; i < 4; ++i) {
                        ull hv = *(const ull*)&XSM(cur, bi + 16 * i, 2 * k2);
                        acc[i][0] = ffma2(hv, p0, acc[i][0]);
                        acc[i][1] = ffma2(hv, p1, acc[i][1]);
                    }
                }
                __syncthreads();
            }
            ull best[4];
#pragma unroll
            for (int i = 0; i < 4; ++i) {
                int b = bi + 16 * i;
                float s0 = fin(acc[i][0]) * alpha + bias;
                float s1 = fin(acc[i][1]) * alpha + bias;
                float* orow = out + ((size_t)b * NT + t) * NCLASS + j0;
                orow[ji] = s0;
                orow[ji + 16] = s1;
                ull k0 = packkey(s0, j0 + ji), k1 = packkey(s1, j0 + ji + 16);
                best[i] = (k0 > k1) ? k0 : k1;
            }
#pragma unroll
            for (int off = 8; off >= 1; off >>= 1)
#pragma unroll
                for (int i = 0; i < 4; ++i) {
                    ull o = __shfl_xor_sync(0xFFFFFFFFu, best[i], off);
                    if (o > best[i]) best[i] = o;
                }
            if (ji == 0)
#pragma unroll
                for (int i = 0; i < 4; ++i) atomicMax(&g_amax[bi + 16 * i], best[i]);
            if (bid == 0 && tid < NB) {   // UNK column
                out[((size_t)tid * NT + t) * NCLASS + NPROTO] = unkscr;
                atomicMax(&g_amax[tid], packkey(unkscr, NPROTO));
            }
        }
        gridbar(phase);
    }
}

// ---------------- launch ----------------
extern "C" void kernel_launch(void* const* d_in, const int* in_sizes, int n_in,
                              void* d_out, int out_size) {
    const float* feature = (const float*)d_in[0];
    const float* A       = (const float*)d_in[1];
    const float* protos  = (const float*)d_in[2];
    const float* semb    = (const float*)d_in[3];
    const float* sta     = (const float*)d_in[4];
    const float* unkv    = (const float*)d_in[5];
    const float* Wih     = (const float*)d_in[6];
    const float* Whh     = (const float*)d_in[7];
    const float* bih     = (const float*)d_in[8];
    const float* bhh     = (const float*)d_in[9];
    const float* alphap  = (const float*)d_in[10];
    const float* biasp   = (const float*)d_in[11];
    const float* unkscrp = (const float*)d_in[12];
    float* out = (float*)d_out;

    cudaFuncSetAttribute(mega, cudaFuncAttributeMaxDynamicSharedMemorySize, SMEM_BYTES);
    mega<<<GRID, TPB, SMEM_BYTES>>>(feature, A, protos, semb, sta, unkv,
                                    Wih, Whh, bih, bhh, alphap, biasp, unkscrp, out);
}